// round 12
// baseline (speedup 1.0000x reference)
#include <cuda_runtime.h>
#include <cuda_fp16.h>
#include <math.h>
#include <stdint.h>

// Problem constants
#define D_MODEL  1024
#define D_HIDDEN 2048
#define N_EXP    8
#define TOPK     2
#define NTOK     8192
#define NPAIR    (NTOK * TOPK)
#define BM       128
#define BNA      128               // stage A n-tile per weight matrix
#define BNB      256               // stage B n-tile
#define BK       16                // k elems per chunk
#define MAXROWS  (NPAIR + N_EXP * BM)   // 17408
#define MTILES   (MAXROWS / BM)         // 136

#define XPH      24                // half pitch, X/H tiles [m][k] (16+8)
#define WPHA     136               // half pitch, stage A W tiles [k][n] (128+8)
#define WPHB     264               // half pitch, stage B W3 tile [k][n] (256+8)

// ---------------- device scratch ----------------
__device__ int    g_row_token[MAXROWS];
__device__ float  g_row_prob[MAXROWS];
__device__ int    g_row_expert[MAXROWS];
__device__ int    g_count[N_EXP];
__device__ int    g_fill[N_EXP];
__device__ float  g_importance[N_EXP];
__device__ int    g_tok_idx[NPAIR];
__device__ float  g_tok_prob[NPAIR];
__device__ __half g_hbuf[(size_t)MAXROWS * D_HIDDEN];
__device__ __half g_xh [(size_t)NTOK * D_MODEL];
__device__ __half g_w1h[(size_t)N_EXP * D_MODEL * D_HIDDEN];
__device__ __half g_w2h[(size_t)N_EXP * D_MODEL * D_HIDDEN];
__device__ __half g_w3h[(size_t)N_EXP * D_HIDDEN * D_MODEL];

// ---------------- PTX helpers ----------------
__device__ __forceinline__ uint32_t smem_u32(const void* p) {
    uint32_t a;
    asm("{ .reg .u64 t; cvta.to.shared.u64 t, %1; cvt.u32.u64 %0, t; }" : "=r"(a) : "l"(p));
    return a;
}
__device__ __forceinline__ uint2 f4_to_h4(float4 v) {
    __half2 lo = __floats2half2_rn(v.x, v.y);
    __half2 hi = __floats2half2_rn(v.z, v.w);
    uint2 r;
    r.x = *(uint32_t*)&lo;
    r.y = *(uint32_t*)&hi;
    return r;
}
__device__ __forceinline__ void cp16(uint32_t dst, const void* src) {
    asm volatile("cp.async.cg.shared.global [%0], [%1], 16;"
                 :: "r"(dst), "l"(src) : "memory");
}
__device__ __forceinline__ void cp16z(uint32_t dst, const void* src, int sz) {
    asm volatile("cp.async.cg.shared.global [%0], [%1], 16, %2;"
                 :: "r"(dst), "l"(src), "r"(sz) : "memory");
}
__device__ __forceinline__ void cp_commit() { asm volatile("cp.async.commit_group;" ::: "memory"); }
__device__ __forceinline__ void cp_wait1()  { asm volatile("cp.async.wait_group 1;" ::: "memory"); }

__device__ __forceinline__ void mma16(float c[4], const uint32_t a[4], uint32_t b0, uint32_t b1) {
    asm volatile(
        "mma.sync.aligned.m16n8k16.row.col.f32.f16.f16.f32 "
        "{%0,%1,%2,%3}, {%4,%5,%6,%7}, {%8,%9}, {%0,%1,%2,%3};"
        : "+f"(c[0]), "+f"(c[1]), "+f"(c[2]), "+f"(c[3])
        : "r"(a[0]), "r"(a[1]), "r"(a[2]), "r"(a[3]), "r"(b0), "r"(b1));
}
__device__ __forceinline__ void ldsm_x4(uint32_t r[4], uint32_t addr) {
    asm volatile("ldmatrix.sync.aligned.m8n8.x4.shared.b16 {%0,%1,%2,%3}, [%4];"
                 : "=r"(r[0]), "=r"(r[1]), "=r"(r[2]), "=r"(r[3]) : "r"(addr));
}
__device__ __forceinline__ void ldsm_x4_t(uint32_t r[4], uint32_t addr) {
    asm volatile("ldmatrix.sync.aligned.m8n8.x4.trans.shared.b16 {%0,%1,%2,%3}, [%4];"
                 : "=r"(r[0]), "=r"(r[1]), "=r"(r[2]), "=r"(r[3]) : "r"(addr));
}

// ---------------- fp32 -> fp16 conversion (x) ----------------
__global__ void f32_to_f16_kernel(const float* __restrict__ src,
                                  __half* __restrict__ dst, int n4) {
    int i = blockIdx.x * blockDim.x + threadIdx.x;
    if (i < n4) {
        float4 v = ((const float4*)src)[i];
        *(uint2*)(dst + (size_t)i * 4) = f4_to_h4(v);
    }
}

// fused weight conversion: w1, w2, w3 in one launch
__global__ void conv_weights_kernel(const float* __restrict__ w1,
                                    const float* __restrict__ w2,
                                    const float* __restrict__ w3, int wn4) {
    int i = blockIdx.x * blockDim.x + threadIdx.x;
    if (i >= 3 * wn4) return;
    const float* src;
    __half* dst;
    int j;
    if (i < wn4)            { src = w1; dst = g_w1h; j = i; }
    else if (i < 2 * wn4)   { src = w2; dst = g_w2h; j = i - wn4; }
    else                    { src = w3; dst = g_w3h; j = i - 2 * wn4; }
    float4 v = ((const float4*)src)[j];
    *(uint2*)(dst + (size_t)j * 4) = f4_to_h4(v);
}

// ---------------- fused reset + output zero ----------------
__global__ void reset_zero_kernel(float* out, int n) {
    int i = blockIdx.x * blockDim.x + threadIdx.x;
    if (i < MAXROWS) {
        g_row_token[i] = -1;
        g_row_prob[i]  = 0.0f;
        g_row_expert[i] = 0;
    }
    if (i < N_EXP) {
        g_count[i] = 0;
        g_fill[i] = 0;
        g_importance[i] = 0.0f;
    }
    if (i < n) out[i] = 0.0f;
}

// ---------------- router: one warp per token ----------------
__global__ void router_kernel(const float* __restrict__ x,
                              const float* __restrict__ gate_w,
                              const float* __restrict__ gate_b) {
    __shared__ float s_imp[N_EXP];
    __shared__ int   s_cnt[N_EXP];
    if (threadIdx.x < N_EXP) { s_imp[threadIdx.x] = 0.0f; s_cnt[threadIdx.x] = 0; }
    __syncthreads();

    int gwarp = (blockIdx.x * blockDim.x + threadIdx.x) >> 5;
    int lane  = threadIdx.x & 31;

    if (gwarp < NTOK) {
        int t = gwarp;
        float acc[N_EXP];
#pragma unroll
        for (int e = 0; e < N_EXP; e++) acc[e] = 0.0f;

        const float* xr = x + (size_t)t * D_MODEL;
        for (int d = lane; d < D_MODEL; d += 32) {
            float xv = xr[d];
            float4 g0 = *(const float4*)(gate_w + (size_t)d * N_EXP);
            float4 g1 = *(const float4*)(gate_w + (size_t)d * N_EXP + 4);
            acc[0] += xv * g0.x; acc[1] += xv * g0.y;
            acc[2] += xv * g0.z; acc[3] += xv * g0.w;
            acc[4] += xv * g1.x; acc[5] += xv * g1.y;
            acc[6] += xv * g1.z; acc[7] += xv * g1.w;
        }
#pragma unroll
        for (int off = 16; off > 0; off >>= 1) {
#pragma unroll
            for (int e = 0; e < N_EXP; e++)
                acc[e] += __shfl_xor_sync(0xffffffffu, acc[e], off);
        }

        if (lane == 0) {
            float logits[N_EXP];
#pragma unroll
            for (int e = 0; e < N_EXP; e++) logits[e] = acc[e] + gate_b[e];

            float m = logits[0];
#pragma unroll
            for (int e = 1; e < N_EXP; e++) m = fmaxf(m, logits[e]);
            float p[N_EXP], s = 0.0f;
#pragma unroll
            for (int e = 0; e < N_EXP; e++) { p[e] = expf(logits[e] - m); s += p[e]; }
            float inv = 1.0f / s;
#pragma unroll
            for (int e = 0; e < N_EXP; e++) atomicAdd(&s_imp[e], p[e] * inv);

            int i1 = 0; float m1 = logits[0];
#pragma unroll
            for (int e = 1; e < N_EXP; e++)
                if (logits[e] > m1) { m1 = logits[e]; i1 = e; }
            int i2 = -1; float m2 = -INFINITY;
#pragma unroll
            for (int e = 0; e < N_EXP; e++)
                if (e != i1 && logits[e] > m2) { m2 = logits[e]; i2 = e; }

            float p1 = 1.0f / (1.0f + expf(m2 - m1));
            g_tok_idx[t * 2]     = i1;
            g_tok_idx[t * 2 + 1] = i2;
            g_tok_prob[t * 2]     = p1;
            g_tok_prob[t * 2 + 1] = 1.0f - p1;
            atomicAdd(&s_cnt[i1], 1);
            atomicAdd(&s_cnt[i2], 1);
        }
    }
    __syncthreads();
    if (threadIdx.x < N_EXP) {
        atomicAdd(&g_importance[threadIdx.x], s_imp[threadIdx.x]);
        atomicAdd(&g_count[threadIdx.x], s_cnt[threadIdx.x]);
    }
}

// ---------------- fused scan + fill + scatter ----------------
__global__ void fill_scatter_kernel() {
    int i = blockIdx.x * blockDim.x + threadIdx.x;
    int seg[N_EXP];
    {
        int off = 0;
#pragma unroll
        for (int e = 0; e < N_EXP; e++) {
            seg[e] = off;
            off += ((g_count[e] + BM - 1) / BM) * BM;
        }
    }
    if (i < MAXROWS) {
        int e = 0;
#pragma unroll
        for (int ee = 1; ee < N_EXP; ee++)
            if (i >= seg[ee]) e = ee;
        g_row_expert[i] = e;
    }
    if (i < NPAIR) {
        int e = g_tok_idx[i];
        int slot = atomicAdd(&g_fill[e], 1);
        int r = seg[e] + slot;
        g_row_token[r] = i >> 1;
        g_row_prob[r]  = g_tok_prob[i];
    }
}

// ---------------- Stage A: h = silu(X w1 + b1) * (X w2 + b2) ----------------
// 128x128(x2) tile, warps 2m x 4n (64x32 per matrix), BK=16, 3-buf cp.async,
// single barrier per chunk, fp16 mma m16n8k16, fp32 accum.
__global__ void __launch_bounds__(256, 1) stageA_kernel(
    const float* __restrict__ b1, const float* __restrict__ b2)
{
    __shared__ __half Xs[3][BM][XPH];      // 18432 B
    __shared__ __half W1s[3][BK][WPHA];    // 13056 B
    __shared__ __half W2s[3][BK][WPHA];    // 13056 B
    __shared__ int    s_tok[BM];

    const int tid = threadIdx.x;
    const int m0 = blockIdx.x * BM;
    const int n0 = blockIdx.y * BNA;
    const int e  = g_row_expert[m0];

    if (tid < BM) s_tok[tid] = g_row_token[m0 + tid];
    __syncthreads();

    // X tile: 128 rows x 32B = 256 granules -> 1/thread
    const int xrr = tid >> 1, xg = (tid & 1) * 8;
    int tok0 = s_tok[xrr];
    const __half* xsrc = (tok0 >= 0) ? (g_xh + (size_t)tok0 * D_MODEL + xg) : g_xh;
    const int xsz = (tok0 >= 0) ? 16 : 0;
    const uint32_t xdst = (uint32_t)((xrr * XPH + xg) * 2);
    // W tiles: 16 rows x 256B = 256 granules -> 1/thread each
    const int wk = tid >> 4, wg = (tid & 15) * 8;
    const __half* w1p = g_w1h + (size_t)e * D_MODEL * D_HIDDEN + n0 + wg;
    const __half* w2p = g_w2h + (size_t)e * D_MODEL * D_HIDDEN + n0 + wg;
    const uint32_t wdst = (uint32_t)((wk * WPHA + wg) * 2);

    const int lane = tid & 31, wid = tid >> 5;
    const int wm = wid & 1, wn = wid >> 1;     // 2 m-warps x 4 n-warps
    const int qr = lane >> 2, qc = lane & 3;

    const uint32_t xs0 = smem_u32(&Xs[0][0][0]);
    const uint32_t aBase = xs0 +
        (uint32_t)(((wm * 64 + (lane & 15)) * XPH + (lane >> 4) * 8) * 2);
    const uint32_t w1s0 = smem_u32(&W1s[0][0][0]);
    const uint32_t w2s0 = smem_u32(&W2s[0][0][0]);
    const uint32_t bOff =
        (uint32_t)(((((lane & 7) + ((lane >> 3) & 1) * 8)) * WPHA + wn * 32 + (lane >> 4) * 8) * 2);

    const uint32_t XBUF = BM * XPH * 2;    // 6144
    const uint32_t WBUF = BK * WPHA * 2;   // 4352

    auto issueA = [&](int c, int buf) {
        int k0 = c * BK;
        cp16z(xs0 + buf * XBUF + xdst, xsrc + k0, xsz);
        cp16(w1s0 + buf * WBUF + wdst, w1p + (size_t)(k0 + wk) * D_HIDDEN);
        cp16(w2s0 + buf * WBUF + wdst, w2p + (size_t)(k0 + wk) * D_HIDDEN);
    };

    float acc1[4][4][4] = {};
    float acc2[4][4][4] = {};

    issueA(0, 0); cp_commit();
    issueA(1, 1); cp_commit();

    const int NCHUNK = D_MODEL / BK;   // 64
    for (int c = 0; c < NCHUNK; c++) {
        const int cur = c % 3;
        cp_wait1();
        __syncthreads();

        uint32_t a[4][4];
#pragma unroll
        for (int mt = 0; mt < 4; mt++)
            ldsm_x4(a[mt], aBase + cur * XBUF + (uint32_t)(mt * 16 * XPH * 2));
#pragma unroll
        for (int p = 0; p < 2; p++) {
            uint32_t t1[4], t2[4];
            uint32_t off = bOff + (uint32_t)(p * 32);
            ldsm_x4_t(t1, w1s0 + cur * WBUF + off);
            ldsm_x4_t(t2, w2s0 + cur * WBUF + off);
#pragma unroll
            for (int mt = 0; mt < 4; mt++) {
                mma16(acc1[mt][2 * p],     a[mt], t1[0], t1[1]);
                mma16(acc1[mt][2 * p + 1], a[mt], t1[2], t1[3]);
                mma16(acc2[mt][2 * p],     a[mt], t2[0], t2[1]);
                mma16(acc2[mt][2 * p + 1], a[mt], t2[2], t2[3]);
            }
        }

        if (c + 2 < NCHUNK) issueA(c + 2, (c + 2) % 3);
        cp_commit();
    }

    // epilogue: C frag c0=(qr,2qc), c1=(qr,2qc+1), c2/c3 row+8
#pragma unroll
    for (int mt = 0; mt < 4; mt++) {
#pragma unroll
        for (int nt = 0; nt < 4; nt++) {
            int colg = n0 + wn * 32 + nt * 8 + 2 * qc;
            float bg0 = b1[e * D_HIDDEN + colg],     bu0 = b2[e * D_HIDDEN + colg];
            float bg1 = b1[e * D_HIDDEN + colg + 1], bu1 = b2[e * D_HIDDEN + colg + 1];
#pragma unroll
            for (int h = 0; h < 2; h++) {
                int row = m0 + wm * 64 + mt * 16 + qr + h * 8;
                float g0 = acc1[mt][nt][2 * h]     + bg0;
                float u0 = acc2[mt][nt][2 * h]     + bu0;
                float g1 = acc1[mt][nt][2 * h + 1] + bg1;
                float u1 = acc2[mt][nt][2 * h + 1] + bu1;
                float h0 = (g0 / (1.0f + expf(-g0))) * u0;
                float h1 = (g1 / (1.0f + expf(-g1))) * u1;
                *(__half2*)&g_hbuf[(size_t)row * D_HIDDEN + colg] =
                    __floats2half2_rn(h0, h1);
            }
        }
    }
}

// ---------------- Stage B: out += prob * (H w3 + b3) ----------------
// 128x256 tile, warps 2m x 4n (64x64), BK=16, 3-buf cp.async.
__global__ void __launch_bounds__(256, 1) stageB_kernel(
    const float* __restrict__ b3, float* __restrict__ out)
{
    __shared__ __half Hs[3][BM][XPH];      // 18432 B
    __shared__ __half W3s[3][BK][WPHB];    // 25344 B
    __shared__ int    s_tok[BM];
    __shared__ float  s_prob[BM];

    const int tid = threadIdx.x;
    const int m0 = blockIdx.x * BM;
    const int n0 = blockIdx.y * BNB;
    const int e  = g_row_expert[m0];

    if (tid < BM) {
        s_tok[tid]  = g_row_token[m0 + tid];
        s_prob[tid] = g_row_prob[m0 + tid];
    }
    __syncthreads();

    // H tile: 256 granules -> 1/thread
    const int hrr = tid >> 1, hg = (tid & 1) * 8;
    const __half* hsrc = g_hbuf + (size_t)(m0 + hrr) * D_HIDDEN + hg;
    const uint32_t hdst = (uint32_t)((hrr * XPH + hg) * 2);
    // W3 tile: 16 rows x 512B = 512 granules -> 2/thread
    uint32_t w3dst[2];
    const __half* w3src[2];
#pragma unroll
    for (int l = 0; l < 2; l++) {
        int idx = tid + l * 256;
        int k = idx >> 5, g = (idx & 31) * 8;
        w3src[l] = g_w3h + (size_t)e * D_HIDDEN * D_MODEL + (size_t)k * D_MODEL + n0 + g;
        w3dst[l] = (uint32_t)((k * WPHB + g) * 2);
    }

    const int lane = tid & 31, wid = tid >> 5;
    const int wm = wid & 1, wn = wid >> 1;     // 2 m-warps x 4 n-warps
    const int qr = lane >> 2, qc = lane & 3;

    const uint32_t hs0 = smem_u32(&Hs[0][0][0]);
    const uint32_t aBase = hs0 +
        (uint32_t)(((wm * 64 + (lane & 15)) * XPH + (lane >> 4) * 8) * 2);
    const uint32_t w3s0 = smem_u32(&W3s[0][0][0]);
    const uint32_t bOff =
        (uint32_t)(((((lane & 7) + ((lane >> 3) & 1) * 8)) * WPHB + wn * 64 + (lane >> 4) * 8) * 2);

    const uint32_t XBUF = BM * XPH * 2;    // 6144
    const uint32_t WBUF = BK * WPHB * 2;   // 8448

    auto issueB = [&](int c, int buf) {
        int k0 = c * BK;
        cp16(hs0 + buf * XBUF + hdst, hsrc + k0);
#pragma unroll
        for (int l = 0; l < 2; l++)
            cp16(w3s0 + buf * WBUF + w3dst[l], w3src[l] + (size_t)k0 * D_MODEL);
    };

    float acc[4][8][4] = {};

    issueB(0, 0); cp_commit();
    issueB(1, 1); cp_commit();

    const int NCHUNK = D_HIDDEN / BK;   // 128
    for (int c = 0; c < NCHUNK; c++) {
        const int cur = c % 3;
        cp_wait1();
        __syncthreads();

        uint32_t a[4][4];
#pragma unroll
        for (int mt = 0; mt < 4; mt++)
            ldsm_x4(a[mt], aBase + cur * XBUF + (uint32_t)(mt * 16 * XPH * 2));
#pragma unroll
        for (int p = 0; p < 4; p++) {
            uint32_t t[4];
            ldsm_x4_t(t, w3s0 + cur * WBUF + bOff + (uint32_t)(p * 32));
#pragma unroll
            for (int mt = 0; mt < 4; mt++) {
                mma16(acc[mt][2 * p],     a[mt], t[0], t[1]);
                mma16(acc[mt][2 * p + 1], a[mt], t[2], t[3]);
            }
        }

        if (c + 2 < NCHUNK) issueB(c + 2, (c + 2) % 3);
        cp_commit();
    }

#pragma unroll
    for (int mt = 0; mt < 4; mt++) {
#pragma unroll
        for (int nt = 0; nt < 8; nt++) {
            int colg = n0 + wn * 64 + nt * 8 + 2 * qc;
            float bv0 = b3[e * D_MODEL + colg];
            float bv1 = b3[e * D_MODEL + colg + 1];
#pragma unroll
            for (int h = 0; h < 2; h++) {
                int rloc = wm * 64 + mt * 16 + qr + h * 8;
                int tok = s_tok[rloc];
                if (tok < 0) continue;
                float p = s_prob[rloc];
                atomicAdd(&out[(size_t)tok * D_MODEL + colg],
                          p * (acc[mt][nt][2 * h] + bv0));
                atomicAdd(&out[(size_t)tok * D_MODEL + colg + 1],
                          p * (acc[mt][nt][2 * h + 1] + bv1));
            }
        }
    }
}

// ---------------- aux loss ----------------
__global__ void aux_kernel(float* out) {
    if (threadIdx.x == 0 && blockIdx.x == 0) {
        float a = 0.0f;
        for (int e = 0; e < N_EXP; e++) {
            float imp = g_importance[e] / (float)NTOK;
            float load = (float)g_count[e] / (float)NPAIR;
            a += imp * load;
        }
        out[(size_t)NTOK * D_MODEL] = a * (float)N_EXP;
    }
}

// ---------------- launch ----------------
extern "C" void kernel_launch(void* const* d_in, const int* in_sizes, int n_in,
                              void* d_out, int out_size) {
    const float* x      = (const float*)d_in[0];
    const float* gate_w = (const float*)d_in[1];
    const float* gate_b = (const float*)d_in[2];
    const float* w1     = (const float*)d_in[3];
    const float* b1     = (const float*)d_in[4];
    const float* w2     = (const float*)d_in[5];
    const float* b2     = (const float*)d_in[6];
    const float* w3     = (const float*)d_in[7];
    const float* b3     = (const float*)d_in[8];
    float* out = (float*)d_out;

    __half* xh; cudaGetSymbolAddress((void**)&xh, g_xh);

    int reset_n = out_size > MAXROWS ? out_size : MAXROWS;
    reset_zero_kernel<<<(reset_n + 255) / 256, 256>>>(out, out_size);

    const int WN4 = N_EXP * D_MODEL * D_HIDDEN / 4;   // 4194304
    const int XN4 = NTOK * D_MODEL / 4;               // 2097152
    f32_to_f16_kernel<<<(XN4 + 255) / 256, 256>>>(x, xh, XN4);
    conv_weights_kernel<<<(3 * WN4 + 255) / 256, 256>>>(w1, w2, w3, WN4);

    router_kernel<<<NTOK / 8, 256>>>(x, gate_w, gate_b);
    fill_scatter_kernel<<<(MAXROWS + 255) / 256, 256>>>();
    stageA_kernel<<<dim3(MTILES, D_HIDDEN / BNA), 256>>>(b1, b2);
    stageB_kernel<<<dim3(MTILES, D_MODEL / BNB), 256>>>(b3, out);
    if (out_size > NTOK * D_MODEL) {
        aux_kernel<<<1, 32>>>(out);
    }
}

// round 13
// speedup vs baseline: 1.3748x; 1.3748x over previous
#include <cuda_runtime.h>
#include <cuda_fp16.h>
#include <math.h>
#include <stdint.h>

// Problem constants
#define D_MODEL  1024
#define D_HIDDEN 2048
#define N_EXP    8
#define TOPK     2
#define NTOK     8192
#define NPAIR    (NTOK * TOPK)
#define BM       128
#define BNA      64                // stage A n-tile per weight matrix
#define BNB      128               // stage B n-tile
#define BK       32
#define MAXROWS  (NPAIR + N_EXP * BM)   // 17408
#define MTILES   (MAXROWS / BM)         // 136
#define NSTG     3

#define XPH      40                // half pitch, X/H tiles [m][k]
#define WPHA     72                // half pitch, stage A W tiles [k][n]
#define WPHB     136               // half pitch, stage B W3 tile [k][n]

#define XS_STAGE  (BM * XPH * 2)        // 10240
#define WA_STAGE  (BK * WPHA * 2)       // 4608
#define WB_STAGE  (BK * WPHB * 2)       // 8704
#define SMEM_A    (NSTG * (XS_STAGE + 2 * WA_STAGE))   // 58368
#define SMEM_B    (NSTG * (XS_STAGE + WB_STAGE))       // 56832

// ---------------- device scratch (keep total < 200MB) ----------------
__device__ int    g_row_token[MAXROWS];
__device__ float  g_row_prob[MAXROWS];
__device__ int    g_row_expert[MAXROWS];
__device__ int    g_count[N_EXP];
__device__ int    g_fill[N_EXP];
__device__ float  g_importance[N_EXP];
__device__ int    g_tok_idx[NPAIR];
__device__ float  g_tok_prob[NPAIR];
__device__ __half g_hbuf[(size_t)MAXROWS * D_HIDDEN];
__device__ __half g_xh [(size_t)NTOK * D_MODEL];
__device__ __half g_w1h[(size_t)N_EXP * D_MODEL * D_HIDDEN];
__device__ __half g_w2h[(size_t)N_EXP * D_MODEL * D_HIDDEN];
__device__ __half g_w3h[(size_t)N_EXP * D_HIDDEN * D_MODEL];

// ---------------- PTX helpers ----------------
__device__ __forceinline__ uint32_t smem_u32(const void* p) {
    uint32_t a;
    asm("{ .reg .u64 t; cvta.to.shared.u64 t, %1; cvt.u32.u64 %0, t; }" : "=r"(a) : "l"(p));
    return a;
}
__device__ __forceinline__ uint2 f4_to_h4(float4 v) {
    __half2 lo = __floats2half2_rn(v.x, v.y);
    __half2 hi = __floats2half2_rn(v.z, v.w);
    uint2 r;
    r.x = *(uint32_t*)&lo;
    r.y = *(uint32_t*)&hi;
    return r;
}
__device__ __forceinline__ void cp16(uint32_t dst, const void* src) {
    asm volatile("cp.async.cg.shared.global [%0], [%1], 16;"
                 :: "r"(dst), "l"(src) : "memory");
}
__device__ __forceinline__ void cp16z(uint32_t dst, const void* src, int sz) {
    asm volatile("cp.async.cg.shared.global [%0], [%1], 16, %2;"
                 :: "r"(dst), "l"(src), "r"(sz) : "memory");
}
__device__ __forceinline__ void cp_commit() { asm volatile("cp.async.commit_group;" ::: "memory"); }
__device__ __forceinline__ void cp_wait1()  { asm volatile("cp.async.wait_group 1;" ::: "memory"); }

__device__ __forceinline__ void mma16(float c[4], const uint32_t a[4], uint32_t b0, uint32_t b1) {
    asm volatile(
        "mma.sync.aligned.m16n8k16.row.col.f32.f16.f16.f32 "
        "{%0,%1,%2,%3}, {%4,%5,%6,%7}, {%8,%9}, {%0,%1,%2,%3};"
        : "+f"(c[0]), "+f"(c[1]), "+f"(c[2]), "+f"(c[3])
        : "r"(a[0]), "r"(a[1]), "r"(a[2]), "r"(a[3]), "r"(b0), "r"(b1));
}
__device__ __forceinline__ void ldsm_x4(uint32_t r[4], uint32_t addr) {
    asm volatile("ldmatrix.sync.aligned.m8n8.x4.shared.b16 {%0,%1,%2,%3}, [%4];"
                 : "=r"(r[0]), "=r"(r[1]), "=r"(r[2]), "=r"(r[3]) : "r"(addr));
}
__device__ __forceinline__ void ldsm_x4_t(uint32_t r[4], uint32_t addr) {
    asm volatile("ldmatrix.sync.aligned.m8n8.x4.trans.shared.b16 {%0,%1,%2,%3}, [%4];"
                 : "=r"(r[0]), "=r"(r[1]), "=r"(r[2]), "=r"(r[3]) : "r"(addr));
}

// ---------------- fused reset + out-zero + fp16 conversion (x, w1, w2, w3) ----------------
#define XN4  (NTOK * D_MODEL / 4)                  // 2097152
#define WN4  (N_EXP * D_MODEL * D_HIDDEN / 4)      // 4194304
#define CONV_TOTAL (XN4 + 3 * WN4)                 // 14680064

__global__ void prep_kernel(const float* __restrict__ x,
                            const float* __restrict__ w1,
                            const float* __restrict__ w2,
                            const float* __restrict__ w3,
                            float* __restrict__ out, int out_n) {
    int i = blockIdx.x * blockDim.x + threadIdx.x;
    if (i < MAXROWS) {
        g_row_token[i] = -1;
        g_row_prob[i]  = 0.0f;
        g_row_expert[i] = 0;
    }
    if (i < N_EXP) {
        g_count[i] = 0;
        g_fill[i] = 0;
        g_importance[i] = 0.0f;
    }
    if (i < out_n) out[i] = 0.0f;
    if (i < CONV_TOTAL) {
        const float* src;
        __half* dst;
        int j;
        if (i < XN4)               { src = x;  dst = g_xh;  j = i; }
        else if (i < XN4 + WN4)    { src = w1; dst = g_w1h; j = i - XN4; }
        else if (i < XN4 + 2*WN4)  { src = w2; dst = g_w2h; j = i - XN4 - WN4; }
        else                       { src = w3; dst = g_w3h; j = i - XN4 - 2*WN4; }
        float4 v = ((const float4*)src)[j];
        *(uint2*)(dst + (size_t)j * 4) = f4_to_h4(v);
    }
}

// ---------------- router: one warp per token ----------------
__global__ void router_kernel(const float* __restrict__ x,
                              const float* __restrict__ gate_w,
                              const float* __restrict__ gate_b) {
    __shared__ float s_imp[N_EXP];
    __shared__ int   s_cnt[N_EXP];
    if (threadIdx.x < N_EXP) { s_imp[threadIdx.x] = 0.0f; s_cnt[threadIdx.x] = 0; }
    __syncthreads();

    int gwarp = (blockIdx.x * blockDim.x + threadIdx.x) >> 5;
    int lane  = threadIdx.x & 31;

    if (gwarp < NTOK) {
        int t = gwarp;
        float acc[N_EXP];
#pragma unroll
        for (int e = 0; e < N_EXP; e++) acc[e] = 0.0f;

        const float* xr = x + (size_t)t * D_MODEL;
        for (int d = lane; d < D_MODEL; d += 32) {
            float xv = xr[d];
            float4 g0 = *(const float4*)(gate_w + (size_t)d * N_EXP);
            float4 g1 = *(const float4*)(gate_w + (size_t)d * N_EXP + 4);
            acc[0] += xv * g0.x; acc[1] += xv * g0.y;
            acc[2] += xv * g0.z; acc[3] += xv * g0.w;
            acc[4] += xv * g1.x; acc[5] += xv * g1.y;
            acc[6] += xv * g1.z; acc[7] += xv * g1.w;
        }
#pragma unroll
        for (int off = 16; off > 0; off >>= 1) {
#pragma unroll
            for (int e = 0; e < N_EXP; e++)
                acc[e] += __shfl_xor_sync(0xffffffffu, acc[e], off);
        }

        if (lane == 0) {
            float logits[N_EXP];
#pragma unroll
            for (int e = 0; e < N_EXP; e++) logits[e] = acc[e] + gate_b[e];

            float m = logits[0];
#pragma unroll
            for (int e = 1; e < N_EXP; e++) m = fmaxf(m, logits[e]);
            float p[N_EXP], s = 0.0f;
#pragma unroll
            for (int e = 0; e < N_EXP; e++) { p[e] = expf(logits[e] - m); s += p[e]; }
            float inv = 1.0f / s;
#pragma unroll
            for (int e = 0; e < N_EXP; e++) atomicAdd(&s_imp[e], p[e] * inv);

            int i1 = 0; float m1 = logits[0];
#pragma unroll
            for (int e = 1; e < N_EXP; e++)
                if (logits[e] > m1) { m1 = logits[e]; i1 = e; }
            int i2 = -1; float m2 = -INFINITY;
#pragma unroll
            for (int e = 0; e < N_EXP; e++)
                if (e != i1 && logits[e] > m2) { m2 = logits[e]; i2 = e; }

            float p1 = 1.0f / (1.0f + expf(m2 - m1));
            g_tok_idx[t * 2]     = i1;
            g_tok_idx[t * 2 + 1] = i2;
            g_tok_prob[t * 2]     = p1;
            g_tok_prob[t * 2 + 1] = 1.0f - p1;
            atomicAdd(&s_cnt[i1], 1);
            atomicAdd(&s_cnt[i2], 1);
        }
    }
    __syncthreads();
    if (threadIdx.x < N_EXP) {
        atomicAdd(&g_importance[threadIdx.x], s_imp[threadIdx.x]);
        atomicAdd(&g_count[threadIdx.x], s_cnt[threadIdx.x]);
    }
}

// ---------------- fused scan + fill + scatter ----------------
__global__ void fill_scatter_kernel() {
    int i = blockIdx.x * blockDim.x + threadIdx.x;
    int seg[N_EXP];
    {
        int off = 0;
#pragma unroll
        for (int e = 0; e < N_EXP; e++) {
            seg[e] = off;
            off += ((g_count[e] + BM - 1) / BM) * BM;
        }
    }
    if (i < MAXROWS) {
        int e = 0;
#pragma unroll
        for (int ee = 1; ee < N_EXP; ee++)
            if (i >= seg[ee]) e = ee;
        g_row_expert[i] = e;
    }
    if (i < NPAIR) {
        int e = g_tok_idx[i];
        int slot = atomicAdd(&g_fill[e], 1);
        int r = seg[e] + slot;
        g_row_token[r] = i >> 1;
        g_row_prob[r]  = g_tok_prob[i];
    }
}

// ---------------- Stage A: h = silu(X w1 + b1) * (X w2 + b2) ----------------
// 128x64(x2), warps 4m x 2n (regs<=128, 2 CTA/SM), BK=32, 3-stage cp.async,
// single barrier per chunk, fp16 mma m16n8k16.
__global__ void __launch_bounds__(256, 2) stageA_kernel(
    const float* __restrict__ b1, const float* __restrict__ b2)
{
    extern __shared__ __half smem[];
    __shared__ int s_tok[BM];

    const int tid = threadIdx.x;
    const int m0 = blockIdx.x * BM;
    const int n0 = blockIdx.y * BNA;
    const int e  = g_row_expert[m0];

    if (tid < BM) s_tok[tid] = g_row_token[m0 + tid];
    __syncthreads();

    const uint32_t xs0  = smem_u32(smem);
    const uint32_t w1s0 = xs0 + NSTG * XS_STAGE;
    const uint32_t w2s0 = w1s0 + NSTG * WA_STAGE;

    // X tile: 128 rows x 64B = 512 granules -> 2/thread
    const __half* xsrc[2];
    int xsz[2];
    uint32_t xdst[2];
#pragma unroll
    for (int l = 0; l < 2; l++) {
        int idx = tid + l * 256;
        int r = idx >> 2, g = idx & 3;
        int tok = s_tok[r];
        xsrc[l] = (tok >= 0) ? (g_xh + (size_t)tok * D_MODEL + g * 8) : g_xh;
        xsz[l]  = (tok >= 0) ? 16 : 0;
        xdst[l] = (uint32_t)((r * XPH + g * 8) * 2);
    }
    // W tiles: 32 rows x 128B = 256 granules -> 1/thread each
    const int wk = tid >> 3, wg = (tid & 7) * 8;
    const __half* w1p = g_w1h + (size_t)e * D_MODEL * D_HIDDEN + n0 + wg;
    const __half* w2p = g_w2h + (size_t)e * D_MODEL * D_HIDDEN + n0 + wg;
    const uint32_t wdst = (uint32_t)((wk * WPHA + wg) * 2);

    const int lane = tid & 31, wid = tid >> 5;
    const int wm = wid & 3, wn = wid >> 2;     // 4 m-warps x 2 n-warps
    const int qr = lane >> 2, qc = lane & 3;

    const uint32_t aBase = xs0 +
        (uint32_t)(((wm * 32 + (lane & 15)) * XPH + (lane >> 4) * 8) * 2);
    const uint32_t bOff =
        (uint32_t)(((((lane & 7) + ((lane >> 3) & 1) * 8)) * WPHA + wn * 32 + (lane >> 4) * 8) * 2);

    auto issueA = [&](int c, int buf) {
        int k0 = c * BK;
#pragma unroll
        for (int l = 0; l < 2; l++)
            cp16z(xs0 + buf * XS_STAGE + xdst[l], xsrc[l] + k0, xsz[l]);
        cp16(w1s0 + buf * WA_STAGE + wdst, w1p + (size_t)(k0 + wk) * D_HIDDEN);
        cp16(w2s0 + buf * WA_STAGE + wdst, w2p + (size_t)(k0 + wk) * D_HIDDEN);
    };

    float acc1[2][4][4] = {};
    float acc2[2][4][4] = {};

    issueA(0, 0); cp_commit();
    issueA(1, 1); cp_commit();

    const int NCHUNK = D_MODEL / BK;   // 32
    for (int c = 0; c < NCHUNK; c++) {
        const int cur = c % NSTG;
        cp_wait1();
        __syncthreads();
#pragma unroll
        for (int step = 0; step < 2; step++) {
            const int kb = step * 16;
            uint32_t a[2][4];
#pragma unroll
            for (int mt = 0; mt < 2; mt++)
                ldsm_x4(a[mt], aBase + cur * XS_STAGE + (uint32_t)((mt * 16 * XPH + kb) * 2));
#pragma unroll
            for (int p = 0; p < 2; p++) {
                uint32_t t1[4], t2[4];
                uint32_t off = bOff + (uint32_t)((kb * WPHA + p * 16) * 2);
                ldsm_x4_t(t1, w1s0 + cur * WA_STAGE + off);
                ldsm_x4_t(t2, w2s0 + cur * WA_STAGE + off);
#pragma unroll
                for (int mt = 0; mt < 2; mt++) {
                    mma16(acc1[mt][2 * p],     a[mt], t1[0], t1[1]);
                    mma16(acc1[mt][2 * p + 1], a[mt], t1[2], t1[3]);
                    mma16(acc2[mt][2 * p],     a[mt], t2[0], t2[1]);
                    mma16(acc2[mt][2 * p + 1], a[mt], t2[2], t2[3]);
                }
            }
        }
        // single barrier per chunk: buffer (c+2)%3 was consumed at iter c-1,
        // and the sync above proves every warp has passed iter c-1.
        if (c + 2 < NCHUNK) issueA(c + 2, (c + 2) % NSTG);
        cp_commit();
    }

    // epilogue
#pragma unroll
    for (int mt = 0; mt < 2; mt++) {
#pragma unroll
        for (int nt = 0; nt < 4; nt++) {
            int colg = n0 + wn * 32 + nt * 8 + 2 * qc;
            float bg0 = b1[e * D_HIDDEN + colg],     bu0 = b2[e * D_HIDDEN + colg];
            float bg1 = b1[e * D_HIDDEN + colg + 1], bu1 = b2[e * D_HIDDEN + colg + 1];
#pragma unroll
            for (int h = 0; h < 2; h++) {
                int row = m0 + wm * 32 + mt * 16 + qr + h * 8;
                float g0 = acc1[mt][nt][2 * h]     + bg0;
                float u0 = acc2[mt][nt][2 * h]     + bu0;
                float g1 = acc1[mt][nt][2 * h + 1] + bg1;
                float u1 = acc2[mt][nt][2 * h + 1] + bu1;
                float h0 = (g0 / (1.0f + expf(-g0))) * u0;
                float h1 = (g1 / (1.0f + expf(-g1))) * u1;
                *(__half2*)&g_hbuf[(size_t)row * D_HIDDEN + colg] =
                    __floats2half2_rn(h0, h1);
            }
        }
    }
}

// ---------------- Stage B: out += prob * (H w3 + b3) ----------------
__global__ void __launch_bounds__(256, 2) stageB_kernel(
    const float* __restrict__ b3, float* __restrict__ out)
{
    extern __shared__ __half smem[];
    __shared__ int   s_tok[BM];
    __shared__ float s_prob[BM];

    const int tid = threadIdx.x;
    const int m0 = blockIdx.x * BM;
    const int n0 = blockIdx.y * BNB;
    const int e  = g_row_expert[m0];

    if (tid < BM) {
        s_tok[tid]  = g_row_token[m0 + tid];
        s_prob[tid] = g_row_prob[m0 + tid];
    }
    __syncthreads();

    const uint32_t hs0  = smem_u32(smem);
    const uint32_t w3s0 = hs0 + NSTG * XS_STAGE;

    // H tile: 512 granules -> 2/thread
    uint32_t hdst[2];
    const __half* hsrc[2];
#pragma unroll
    for (int l = 0; l < 2; l++) {
        int idx = tid + l * 256;
        int r = idx >> 2, g = idx & 3;
        hsrc[l] = g_hbuf + (size_t)(m0 + r) * D_HIDDEN + g * 8;
        hdst[l] = (uint32_t)((r * XPH + g * 8) * 2);
    }
    // W3 tile: 32 rows x 256B = 512 granules -> 2/thread
    uint32_t w3dst[2];
    const __half* w3src[2];
#pragma unroll
    for (int l = 0; l < 2; l++) {
        int idx = tid + l * 256;
        int k = idx >> 4, g = (idx & 15) * 8;
        w3src[l] = g_w3h + (size_t)e * D_HIDDEN * D_MODEL + (size_t)k * D_MODEL + n0 + g;
        w3dst[l] = (uint32_t)((k * WPHB + g) * 2);
    }

    const int lane = tid & 31, wid = tid >> 5;
    const int wm = wid & 3, wn = wid >> 2;
    const int qr = lane >> 2, qc = lane & 3;

    const uint32_t aBase = hs0 +
        (uint32_t)(((wm * 32 + (lane & 15)) * XPH + (lane >> 4) * 8) * 2);
    const uint32_t bOff =
        (uint32_t)(((((lane & 7) + ((lane >> 3) & 1) * 8)) * WPHB + wn * 64 + (lane >> 4) * 8) * 2);

    auto issueB = [&](int c, int buf) {
        int k0 = c * BK;
#pragma unroll
        for (int l = 0; l < 2; l++)
            cp16(hs0 + buf * XS_STAGE + hdst[l], hsrc[l] + k0);
#pragma unroll
        for (int l = 0; l < 2; l++)
            cp16(w3s0 + buf * WB_STAGE + w3dst[l], w3src[l] + (size_t)k0 * D_MODEL);
    };

    float acc[2][8][4] = {};

    issueB(0, 0); cp_commit();
    issueB(1, 1); cp_commit();

    const int NCHUNK = D_HIDDEN / BK;   // 64
    for (int c = 0; c < NCHUNK; c++) {
        const int cur = c % NSTG;
        cp_wait1();
        __syncthreads();
#pragma unroll
        for (int step = 0; step < 2; step++) {
            const int kb = step * 16;
            uint32_t a[2][4];
#pragma unroll
            for (int mt = 0; mt < 2; mt++)
                ldsm_x4(a[mt], aBase + cur * XS_STAGE + (uint32_t)((mt * 16 * XPH + kb) * 2));
#pragma unroll
            for (int p = 0; p < 4; p++) {
                uint32_t t[4];
                ldsm_x4_t(t, w3s0 + cur * WB_STAGE + bOff + (uint32_t)((kb * WPHB + p * 16) * 2));
#pragma unroll
                for (int mt = 0; mt < 2; mt++) {
                    mma16(acc[mt][2 * p],     a[mt], t[0], t[1]);
                    mma16(acc[mt][2 * p + 1], a[mt], t[2], t[3]);
                }
            }
        }
        if (c + 2 < NCHUNK) issueB(c + 2, (c + 2) % NSTG);
        cp_commit();
    }

#pragma unroll
    for (int mt = 0; mt < 2; mt++) {
#pragma unroll
        for (int nt = 0; nt < 8; nt++) {
            int colg = n0 + wn * 64 + nt * 8 + 2 * qc;
            float bv0 = b3[e * D_MODEL + colg];
            float bv1 = b3[e * D_MODEL + colg + 1];
#pragma unroll
            for (int h = 0; h < 2; h++) {
                int rloc = wm * 32 + mt * 16 + qr + h * 8;
                int tok = s_tok[rloc];
                if (tok < 0) continue;
                float p = s_prob[rloc];
                atomicAdd(&out[(size_t)tok * D_MODEL + colg],
                          p * (acc[mt][nt][2 * h] + bv0));
                atomicAdd(&out[(size_t)tok * D_MODEL + colg + 1],
                          p * (acc[mt][nt][2 * h + 1] + bv1));
            }
        }
    }
}

// ---------------- aux loss ----------------
__global__ void aux_kernel(float* out) {
    if (threadIdx.x == 0 && blockIdx.x == 0) {
        float a = 0.0f;
        for (int e = 0; e < N_EXP; e++) {
            float imp = g_importance[e] / (float)NTOK;
            float load = (float)g_count[e] / (float)NPAIR;
            a += imp * load;
        }
        out[(size_t)NTOK * D_MODEL] = a * (float)N_EXP;
    }
}

// ---------------- launch ----------------
extern "C" void kernel_launch(void* const* d_in, const int* in_sizes, int n_in,
                              void* d_out, int out_size) {
    const float* x      = (const float*)d_in[0];
    const float* gate_w = (const float*)d_in[1];
    const float* gate_b = (const float*)d_in[2];
    const float* w1     = (const float*)d_in[3];
    const float* b1     = (const float*)d_in[4];
    const float* w2     = (const float*)d_in[5];
    const float* b2     = (const float*)d_in[6];
    const float* w3     = (const float*)d_in[7];
    const float* b3     = (const float*)d_in[8];
    float* out = (float*)d_out;

    cudaFuncSetAttribute(stageA_kernel, cudaFuncAttributeMaxDynamicSharedMemorySize, SMEM_A);
    cudaFuncSetAttribute(stageB_kernel, cudaFuncAttributeMaxDynamicSharedMemorySize, SMEM_B);

    // launch index 3 = stageA (ncu capture slot)
    prep_kernel<<<(CONV_TOTAL + 255) / 256, 256>>>(x, w1, w2, w3, out, out_size);
    router_kernel<<<NTOK / 8, 256>>>(x, gate_w, gate_b);
    fill_scatter_kernel<<<(MAXROWS + 255) / 256, 256>>>();
    stageA_kernel<<<dim3(MTILES, D_HIDDEN / BNA), 256, SMEM_A>>>(b1, b2);
    stageB_kernel<<<dim3(MTILES, D_MODEL / BNB), 256, SMEM_B>>>(b3, out);
    if (out_size > NTOK * D_MODEL) {
        aux_kernel<<<1, 32>>>(out);
    }
}

// round 14
// speedup vs baseline: 1.4514x; 1.0557x over previous
#include <cuda_runtime.h>
#include <cuda_fp16.h>
#include <math.h>
#include <stdint.h>

// Problem constants
#define D_MODEL  1024
#define D_HIDDEN 2048
#define N_EXP    8
#define TOPK     2
#define NTOK     8192
#define NPAIR    (NTOK * TOPK)
#define BM       128
#define BNA      64                // stage A n-tile per weight matrix
#define BNB      128               // stage B n-tile
#define BK       32
#define MAXROWS  (NPAIR + N_EXP * BM)   // 17408
#define MTILES   (MAXROWS / BM)         // 136
#define NSTG     4

#define XPH      40                // half pitch, X/H tiles [m][k]
#define WPHA     72                // half pitch, stage A W tiles [k][n]
#define WPHB     136               // half pitch, stage B W3 tile [k][n]

#define XS_STAGE  (BM * XPH * 2)        // 10240
#define WA_STAGE  (BK * WPHA * 2)       // 4608
#define WB_STAGE  (BK * WPHB * 2)       // 8704
#define SMEM_A    (NSTG * (XS_STAGE + 2 * WA_STAGE))   // 77824
#define SMEM_B    (NSTG * (XS_STAGE + WB_STAGE))       // 75776

// ---------------- device scratch (keep total < 200MB) ----------------
__device__ int    g_row_token[MAXROWS];
__device__ float  g_row_prob[MAXROWS];
__device__ int    g_row_expert[MAXROWS];
__device__ int    g_count[N_EXP];
__device__ int    g_fill[N_EXP];
__device__ float  g_importance[N_EXP];
__device__ int    g_tok_idx[NPAIR];
__device__ float  g_tok_prob[NPAIR];
__device__ __half g_hbuf[(size_t)MAXROWS * D_HIDDEN];
__device__ __half g_xh [(size_t)NTOK * D_MODEL];
__device__ __half g_w1h[(size_t)N_EXP * D_MODEL * D_HIDDEN];
__device__ __half g_w2h[(size_t)N_EXP * D_MODEL * D_HIDDEN];
__device__ __half g_w3h[(size_t)N_EXP * D_HIDDEN * D_MODEL];

// ---------------- PTX helpers ----------------
__device__ __forceinline__ uint32_t smem_u32(const void* p) {
    uint32_t a;
    asm("{ .reg .u64 t; cvta.to.shared.u64 t, %1; cvt.u32.u64 %0, t; }" : "=r"(a) : "l"(p));
    return a;
}
__device__ __forceinline__ uint2 f4_to_h4(float4 v) {
    __half2 lo = __floats2half2_rn(v.x, v.y);
    __half2 hi = __floats2half2_rn(v.z, v.w);
    uint2 r;
    r.x = *(uint32_t*)&lo;
    r.y = *(uint32_t*)&hi;
    return r;
}
__device__ __forceinline__ void cp16(uint32_t dst, const void* src) {
    asm volatile("cp.async.cg.shared.global [%0], [%1], 16;"
                 :: "r"(dst), "l"(src) : "memory");
}
__device__ __forceinline__ void cp16z(uint32_t dst, const void* src, int sz) {
    asm volatile("cp.async.cg.shared.global [%0], [%1], 16, %2;"
                 :: "r"(dst), "l"(src), "r"(sz) : "memory");
}
__device__ __forceinline__ void cp_commit() { asm volatile("cp.async.commit_group;" ::: "memory"); }
__device__ __forceinline__ void cp_wait2()  { asm volatile("cp.async.wait_group 2;" ::: "memory"); }

__device__ __forceinline__ void mma16(float c[4], const uint32_t a[4], uint32_t b0, uint32_t b1) {
    asm volatile(
        "mma.sync.aligned.m16n8k16.row.col.f32.f16.f16.f32 "
        "{%0,%1,%2,%3}, {%4,%5,%6,%7}, {%8,%9}, {%0,%1,%2,%3};"
        : "+f"(c[0]), "+f"(c[1]), "+f"(c[2]), "+f"(c[3])
        : "r"(a[0]), "r"(a[1]), "r"(a[2]), "r"(a[3]), "r"(b0), "r"(b1));
}
__device__ __forceinline__ void ldsm_x4(uint32_t r[4], uint32_t addr) {
    asm volatile("ldmatrix.sync.aligned.m8n8.x4.shared.b16 {%0,%1,%2,%3}, [%4];"
                 : "=r"(r[0]), "=r"(r[1]), "=r"(r[2]), "=r"(r[3]) : "r"(addr));
}
__device__ __forceinline__ void ldsm_x4_t(uint32_t r[4], uint32_t addr) {
    asm volatile("ldmatrix.sync.aligned.m8n8.x4.trans.shared.b16 {%0,%1,%2,%3}, [%4];"
                 : "=r"(r[0]), "=r"(r[1]), "=r"(r[2]), "=r"(r[3]) : "r"(addr));
}

// ---------------- fused reset + out-zero + fp16 conversion ----------------
#define XN4  (NTOK * D_MODEL / 4)                  // 2097152
#define WN4  (N_EXP * D_MODEL * D_HIDDEN / 4)      // 4194304
#define CONV_TOTAL (XN4 + 3 * WN4)                 // 14680064

__global__ void prep_kernel(const float* __restrict__ x,
                            const float* __restrict__ w1,
                            const float* __restrict__ w2,
                            const float* __restrict__ w3,
                            float* __restrict__ out, int out_n) {
    int i = blockIdx.x * blockDim.x + threadIdx.x;
    if (i < MAXROWS) {
        g_row_token[i] = -1;
        g_row_prob[i]  = 0.0f;
        g_row_expert[i] = 0;
    }
    if (i < N_EXP) {
        g_count[i] = 0;
        g_fill[i] = 0;
        g_importance[i] = 0.0f;
    }
    if (i < out_n) out[i] = 0.0f;
    if (i < CONV_TOTAL) {
        const float* src;
        __half* dst;
        int j;
        if (i < XN4)               { src = x;  dst = g_xh;  j = i; }
        else if (i < XN4 + WN4)    { src = w1; dst = g_w1h; j = i - XN4; }
        else if (i < XN4 + 2*WN4)  { src = w2; dst = g_w2h; j = i - XN4 - WN4; }
        else                       { src = w3; dst = g_w3h; j = i - XN4 - 2*WN4; }
        float4 v = ((const float4*)src)[j];
        *(uint2*)(dst + (size_t)j * 4) = f4_to_h4(v);
    }
}

// ---------------- router: one warp per token ----------------
__global__ void router_kernel(const float* __restrict__ x,
                              const float* __restrict__ gate_w,
                              const float* __restrict__ gate_b) {
    __shared__ float s_imp[N_EXP];
    __shared__ int   s_cnt[N_EXP];
    if (threadIdx.x < N_EXP) { s_imp[threadIdx.x] = 0.0f; s_cnt[threadIdx.x] = 0; }
    __syncthreads();

    int gwarp = (blockIdx.x * blockDim.x + threadIdx.x) >> 5;
    int lane  = threadIdx.x & 31;

    if (gwarp < NTOK) {
        int t = gwarp;
        float acc[N_EXP];
#pragma unroll
        for (int e = 0; e < N_EXP; e++) acc[e] = 0.0f;

        const float* xr = x + (size_t)t * D_MODEL;
        for (int d = lane; d < D_MODEL; d += 32) {
            float xv = xr[d];
            float4 g0 = *(const float4*)(gate_w + (size_t)d * N_EXP);
            float4 g1 = *(const float4*)(gate_w + (size_t)d * N_EXP + 4);
            acc[0] += xv * g0.x; acc[1] += xv * g0.y;
            acc[2] += xv * g0.z; acc[3] += xv * g0.w;
            acc[4] += xv * g1.x; acc[5] += xv * g1.y;
            acc[6] += xv * g1.z; acc[7] += xv * g1.w;
        }
#pragma unroll
        for (int off = 16; off > 0; off >>= 1) {
#pragma unroll
            for (int e = 0; e < N_EXP; e++)
                acc[e] += __shfl_xor_sync(0xffffffffu, acc[e], off);
        }

        if (lane == 0) {
            float logits[N_EXP];
#pragma unroll
            for (int e = 0; e < N_EXP; e++) logits[e] = acc[e] + gate_b[e];

            float m = logits[0];
#pragma unroll
            for (int e = 1; e < N_EXP; e++) m = fmaxf(m, logits[e]);
            float p[N_EXP], s = 0.0f;
#pragma unroll
            for (int e = 0; e < N_EXP; e++) { p[e] = expf(logits[e] - m); s += p[e]; }
            float inv = 1.0f / s;
#pragma unroll
            for (int e = 0; e < N_EXP; e++) atomicAdd(&s_imp[e], p[e] * inv);

            int i1 = 0; float m1 = logits[0];
#pragma unroll
            for (int e = 1; e < N_EXP; e++)
                if (logits[e] > m1) { m1 = logits[e]; i1 = e; }
            int i2 = -1; float m2 = -INFINITY;
#pragma unroll
            for (int e = 0; e < N_EXP; e++)
                if (e != i1 && logits[e] > m2) { m2 = logits[e]; i2 = e; }

            float p1 = 1.0f / (1.0f + expf(m2 - m1));
            g_tok_idx[t * 2]     = i1;
            g_tok_idx[t * 2 + 1] = i2;
            g_tok_prob[t * 2]     = p1;
            g_tok_prob[t * 2 + 1] = 1.0f - p1;
            atomicAdd(&s_cnt[i1], 1);
            atomicAdd(&s_cnt[i2], 1);
        }
    }
    __syncthreads();
    if (threadIdx.x < N_EXP) {
        atomicAdd(&g_importance[threadIdx.x], s_imp[threadIdx.x]);
        atomicAdd(&g_count[threadIdx.x], s_cnt[threadIdx.x]);
    }
}

// ---------------- fused scan + fill + scatter ----------------
__global__ void fill_scatter_kernel() {
    int i = blockIdx.x * blockDim.x + threadIdx.x;
    int seg[N_EXP];
    {
        int off = 0;
#pragma unroll
        for (int e = 0; e < N_EXP; e++) {
            seg[e] = off;
            off += ((g_count[e] + BM - 1) / BM) * BM;
        }
    }
    if (i < MAXROWS) {
        int e = 0;
#pragma unroll
        for (int ee = 1; ee < N_EXP; ee++)
            if (i >= seg[ee]) e = ee;
        g_row_expert[i] = e;
    }
    if (i < NPAIR) {
        int e = g_tok_idx[i];
        int slot = atomicAdd(&g_fill[e], 1);
        int r = seg[e] + slot;
        g_row_token[r] = i >> 1;
        g_row_prob[r]  = g_tok_prob[i];
    }
}

// ---------------- Stage A: h = silu(X w1 + b1) * (X w2 + b2) ----------------
// 128x64(x2), warps 4m x 2n, BK=32, 4-stage cp.async (2 chunks in flight),
// single barrier per chunk, fp16 mma m16n8k16.
__global__ void __launch_bounds__(256, 2) stageA_kernel(
    const float* __restrict__ b1, const float* __restrict__ b2)
{
    extern __shared__ __half smem[];
    __shared__ int s_tok[BM];

    const int tid = threadIdx.x;
    const int m0 = blockIdx.x * BM;
    const int n0 = blockIdx.y * BNA;
    const int e  = g_row_expert[m0];

    if (tid < BM) s_tok[tid] = g_row_token[m0 + tid];
    __syncthreads();

    const uint32_t xs0  = smem_u32(smem);
    const uint32_t w1s0 = xs0 + NSTG * XS_STAGE;
    const uint32_t w2s0 = w1s0 + NSTG * WA_STAGE;

    // X tile: 128 rows x 64B = 512 granules -> 2/thread
    const __half* xsrc[2];
    int xsz[2];
    uint32_t xdst[2];
#pragma unroll
    for (int l = 0; l < 2; l++) {
        int idx = tid + l * 256;
        int r = idx >> 2, g = idx & 3;
        int tok = s_tok[r];
        xsrc[l] = (tok >= 0) ? (g_xh + (size_t)tok * D_MODEL + g * 8) : g_xh;
        xsz[l]  = (tok >= 0) ? 16 : 0;
        xdst[l] = (uint32_t)((r * XPH + g * 8) * 2);
    }
    // W tiles: 32 rows x 128B = 256 granules -> 1/thread each
    const int wk = tid >> 3, wg = (tid & 7) * 8;
    const __half* w1p = g_w1h + (size_t)e * D_MODEL * D_HIDDEN + n0 + wg;
    const __half* w2p = g_w2h + (size_t)e * D_MODEL * D_HIDDEN + n0 + wg;
    const uint32_t wdst = (uint32_t)((wk * WPHA + wg) * 2);

    const int lane = tid & 31, wid = tid >> 5;
    const int wm = wid & 3, wn = wid >> 2;     // 4 m-warps x 2 n-warps
    const int qr = lane >> 2, qc = lane & 3;

    const uint32_t aBase = xs0 +
        (uint32_t)(((wm * 32 + (lane & 15)) * XPH + (lane >> 4) * 8) * 2);
    const uint32_t bOff =
        (uint32_t)(((((lane & 7) + ((lane >> 3) & 1) * 8)) * WPHA + wn * 32 + (lane >> 4) * 8) * 2);

    auto issueA = [&](int c, int buf) {
        int k0 = c * BK;
#pragma unroll
        for (int l = 0; l < 2; l++)
            cp16z(xs0 + buf * XS_STAGE + xdst[l], xsrc[l] + k0, xsz[l]);
        cp16(w1s0 + buf * WA_STAGE + wdst, w1p + (size_t)(k0 + wk) * D_HIDDEN);
        cp16(w2s0 + buf * WA_STAGE + wdst, w2p + (size_t)(k0 + wk) * D_HIDDEN);
    };

    float acc1[2][4][4] = {};
    float acc2[2][4][4] = {};

    issueA(0, 0); cp_commit();
    issueA(1, 1); cp_commit();
    issueA(2, 2); cp_commit();

    const int NCHUNK = D_MODEL / BK;   // 32
    for (int c = 0; c < NCHUNK; c++) {
        const int cur = c % NSTG;
        cp_wait2();
        __syncthreads();
#pragma unroll
        for (int step = 0; step < 2; step++) {
            const int kb = step * 16;
            uint32_t a[2][4];
#pragma unroll
            for (int mt = 0; mt < 2; mt++)
                ldsm_x4(a[mt], aBase + cur * XS_STAGE + (uint32_t)((mt * 16 * XPH + kb) * 2));
#pragma unroll
            for (int p = 0; p < 2; p++) {
                uint32_t t1[4], t2[4];
                uint32_t off = bOff + (uint32_t)((kb * WPHA + p * 16) * 2);
                ldsm_x4_t(t1, w1s0 + cur * WA_STAGE + off);
                ldsm_x4_t(t2, w2s0 + cur * WA_STAGE + off);
#pragma unroll
                for (int mt = 0; mt < 2; mt++) {
                    mma16(acc1[mt][2 * p],     a[mt], t1[0], t1[1]);
                    mma16(acc1[mt][2 * p + 1], a[mt], t1[2], t1[3]);
                    mma16(acc2[mt][2 * p],     a[mt], t2[0], t2[1]);
                    mma16(acc2[mt][2 * p + 1], a[mt], t2[2], t2[3]);
                }
            }
        }
        // buffer (c+3)%4 was consumed at iter c-1; top barrier fences it.
        if (c + 3 < NCHUNK) issueA(c + 3, (c + 3) % NSTG);
        cp_commit();
    }

    // epilogue
#pragma unroll
    for (int mt = 0; mt < 2; mt++) {
#pragma unroll
        for (int nt = 0; nt < 4; nt++) {
            int colg = n0 + wn * 32 + nt * 8 + 2 * qc;
            float bg0 = b1[e * D_HIDDEN + colg],     bu0 = b2[e * D_HIDDEN + colg];
            float bg1 = b1[e * D_HIDDEN + colg + 1], bu1 = b2[e * D_HIDDEN + colg + 1];
#pragma unroll
            for (int h = 0; h < 2; h++) {
                int row = m0 + wm * 32 + mt * 16 + qr + h * 8;
                float g0 = acc1[mt][nt][2 * h]     + bg0;
                float u0 = acc2[mt][nt][2 * h]     + bu0;
                float g1 = acc1[mt][nt][2 * h + 1] + bg1;
                float u1 = acc2[mt][nt][2 * h + 1] + bu1;
                float h0 = (g0 / (1.0f + expf(-g0))) * u0;
                float h1 = (g1 / (1.0f + expf(-g1))) * u1;
                *(__half2*)&g_hbuf[(size_t)row * D_HIDDEN + colg] =
                    __floats2half2_rn(h0, h1);
            }
        }
    }
}

// ---------------- Stage B: out += prob * (H w3 + b3) ----------------
__global__ void __launch_bounds__(256, 2) stageB_kernel(
    const float* __restrict__ b3, float* __restrict__ out)
{
    extern __shared__ __half smem[];
    __shared__ int   s_tok[BM];
    __shared__ float s_prob[BM];

    const int tid = threadIdx.x;
    const int m0 = blockIdx.x * BM;
    const int n0 = blockIdx.y * BNB;
    const int e  = g_row_expert[m0];

    if (tid < BM) {
        s_tok[tid]  = g_row_token[m0 + tid];
        s_prob[tid] = g_row_prob[m0 + tid];
    }
    __syncthreads();

    const uint32_t hs0  = smem_u32(smem);
    const uint32_t w3s0 = hs0 + NSTG * XS_STAGE;

    // H tile: 512 granules -> 2/thread
    uint32_t hdst[2];
    const __half* hsrc[2];
#pragma unroll
    for (int l = 0; l < 2; l++) {
        int idx = tid + l * 256;
        int r = idx >> 2, g = idx & 3;
        hsrc[l] = g_hbuf + (size_t)(m0 + r) * D_HIDDEN + g * 8;
        hdst[l] = (uint32_t)((r * XPH + g * 8) * 2);
    }
    // W3 tile: 32 rows x 256B = 512 granules -> 2/thread
    uint32_t w3dst[2];
    const __half* w3src[2];
#pragma unroll
    for (int l = 0; l < 2; l++) {
        int idx = tid + l * 256;
        int k = idx >> 4, g = (idx & 15) * 8;
        w3src[l] = g_w3h + (size_t)e * D_HIDDEN * D_MODEL + (size_t)k * D_MODEL + n0 + g;
        w3dst[l] = (uint32_t)((k * WPHB + g) * 2);
    }

    const int lane = tid & 31, wid = tid >> 5;
    const int wm = wid & 3, wn = wid >> 2;
    const int qr = lane >> 2, qc = lane & 3;

    const uint32_t aBase = hs0 +
        (uint32_t)(((wm * 32 + (lane & 15)) * XPH + (lane >> 4) * 8) * 2);
    const uint32_t bOff =
        (uint32_t)(((((lane & 7) + ((lane >> 3) & 1) * 8)) * WPHB + wn * 64 + (lane >> 4) * 8) * 2);

    auto issueB = [&](int c, int buf) {
        int k0 = c * BK;
#pragma unroll
        for (int l = 0; l < 2; l++)
            cp16(hs0 + buf * XS_STAGE + hdst[l], hsrc[l] + k0);
#pragma unroll
        for (int l = 0; l < 2; l++)
            cp16(w3s0 + buf * WB_STAGE + w3dst[l], w3src[l] + (size_t)k0 * D_MODEL);
    };

    float acc[2][8][4] = {};

    issueB(0, 0); cp_commit();
    issueB(1, 1); cp_commit();
    issueB(2, 2); cp_commit();

    const int NCHUNK = D_HIDDEN / BK;   // 64
    for (int c = 0; c < NCHUNK; c++) {
        const int cur = c % NSTG;
        cp_wait2();
        __syncthreads();
#pragma unroll
        for (int step = 0; step < 2; step++) {
            const int kb = step * 16;
            uint32_t a[2][4];
#pragma unroll
            for (int mt = 0; mt < 2; mt++)
                ldsm_x4(a[mt], aBase + cur * XS_STAGE + (uint32_t)((mt * 16 * XPH + kb) * 2));
#pragma unroll
            for (int p = 0; p < 4; p++) {
                uint32_t t[4];
                ldsm_x4_t(t, w3s0 + cur * WB_STAGE + bOff + (uint32_t)((kb * WPHB + p * 16) * 2));
#pragma unroll
                for (int mt = 0; mt < 2; mt++) {
                    mma16(acc[mt][2 * p],     a[mt], t[0], t[1]);
                    mma16(acc[mt][2 * p + 1], a[mt], t[2], t[3]);
                }
            }
        }
        if (c + 3 < NCHUNK) issueB(c + 3, (c + 3) % NSTG);
        cp_commit();
    }

#pragma unroll
    for (int mt = 0; mt < 2; mt++) {
#pragma unroll
        for (int nt = 0; nt < 8; nt++) {
            int colg = n0 + wn * 64 + nt * 8 + 2 * qc;
            float bv0 = b3[e * D_MODEL + colg];
            float bv1 = b3[e * D_MODEL + colg + 1];
#pragma unroll
            for (int h = 0; h < 2; h++) {
                int rloc = wm * 32 + mt * 16 + qr + h * 8;
                int tok = s_tok[rloc];
                if (tok < 0) continue;
                float p = s_prob[rloc];
                atomicAdd(&out[(size_t)tok * D_MODEL + colg],
                          p * (acc[mt][nt][2 * h] + bv0));
                atomicAdd(&out[(size_t)tok * D_MODEL + colg + 1],
                          p * (acc[mt][nt][2 * h + 1] + bv1));
            }
        }
    }
}

// ---------------- aux loss ----------------
__global__ void aux_kernel(float* out) {
    if (threadIdx.x == 0 && blockIdx.x == 0) {
        float a = 0.0f;
        for (int e = 0; e < N_EXP; e++) {
            float imp = g_importance[e] / (float)NTOK;
            float load = (float)g_count[e] / (float)NPAIR;
            a += imp * load;
        }
        out[(size_t)NTOK * D_MODEL] = a * (float)N_EXP;
    }
}

// ---------------- launch ----------------
extern "C" void kernel_launch(void* const* d_in, const int* in_sizes, int n_in,
                              void* d_out, int out_size) {
    const float* x      = (const float*)d_in[0];
    const float* gate_w = (const float*)d_in[1];
    const float* gate_b = (const float*)d_in[2];
    const float* w1     = (const float*)d_in[3];
    const float* b1     = (const float*)d_in[4];
    const float* w2     = (const float*)d_in[5];
    const float* b2     = (const float*)d_in[6];
    const float* w3     = (const float*)d_in[7];
    const float* b3     = (const float*)d_in[8];
    float* out = (float*)d_out;

    cudaFuncSetAttribute(stageA_kernel, cudaFuncAttributeMaxDynamicSharedMemorySize, SMEM_A);
    cudaFuncSetAttribute(stageB_kernel, cudaFuncAttributeMaxDynamicSharedMemorySize, SMEM_B);

    // launch index 3 = stageA (ncu capture slot)
    prep_kernel<<<(CONV_TOTAL + 255) / 256, 256>>>(x, w1, w2, w3, out, out_size);
    router_kernel<<<NTOK / 8, 256>>>(x, gate_w, gate_b);
    fill_scatter_kernel<<<(MAXROWS + 255) / 256, 256>>>();
    stageA_kernel<<<dim3(MTILES, D_HIDDEN / BNA), 256, SMEM_A>>>(b1, b2);
    stageB_kernel<<<dim3(MTILES, D_MODEL / BNB), 256, SMEM_B>>>(b3, out);
    if (out_size > NTOK * D_MODEL) {
        aux_kernel<<<1, 32>>>(out);
    }
}

// round 15
// speedup vs baseline: 1.4611x; 1.0067x over previous
#include <cuda_runtime.h>
#include <cuda_fp16.h>
#include <math.h>
#include <stdint.h>

// Problem constants
#define D_MODEL  1024
#define D_HIDDEN 2048
#define N_EXP    8
#define TOPK     2
#define NTOK     8192
#define NPAIR    (NTOK * TOPK)
#define BM       128
#define BNA      64                // stage A n-tile per weight matrix
#define BNB      128               // stage B n-tile
#define BK       64
#define MAXROWS  (NPAIR + N_EXP * BM)   // 17408
#define MTILES   (MAXROWS / BM)         // 136
#define NSTG     3

#define XPH      72                // half pitch, X/H tiles [m][k] (64+8)
#define WPHA     72                // half pitch, stage A W tiles [k][n] (64+8)
#define WPHB     136               // half pitch, stage B W3 tile [k][n] (128+8)

#define XS_STAGE  (BM * XPH * 2)        // 18432
#define WA_STAGE  (BK * WPHA * 2)       // 9216
#define WB_STAGE  (BK * WPHB * 2)       // 17408
#define SMEM_A    (NSTG * (XS_STAGE + 2 * WA_STAGE))   // 110592
#define SMEM_B    (NSTG * (XS_STAGE + WB_STAGE))       // 107520

// ---------------- device scratch (keep total < 200MB) ----------------
__device__ int    g_row_token[MAXROWS];
__device__ float  g_row_prob[MAXROWS];
__device__ int    g_row_expert[MAXROWS];
__device__ int    g_count[N_EXP];
__device__ int    g_fill[N_EXP];
__device__ float  g_importance[N_EXP];
__device__ int    g_tok_idx[NPAIR];
__device__ float  g_tok_prob[NPAIR];
__device__ __half g_hbuf[(size_t)MAXROWS * D_HIDDEN];
__device__ __half g_xh [(size_t)NTOK * D_MODEL];
__device__ __half g_w1h[(size_t)N_EXP * D_MODEL * D_HIDDEN];
__device__ __half g_w2h[(size_t)N_EXP * D_MODEL * D_HIDDEN];
__device__ __half g_w3h[(size_t)N_EXP * D_HIDDEN * D_MODEL];

// ---------------- PTX helpers ----------------
__device__ __forceinline__ uint32_t smem_u32(const void* p) {
    uint32_t a;
    asm("{ .reg .u64 t; cvta.to.shared.u64 t, %1; cvt.u32.u64 %0, t; }" : "=r"(a) : "l"(p));
    return a;
}
__device__ __forceinline__ uint2 f4_to_h4(float4 v) {
    __half2 lo = __floats2half2_rn(v.x, v.y);
    __half2 hi = __floats2half2_rn(v.z, v.w);
    uint2 r;
    r.x = *(uint32_t*)&lo;
    r.y = *(uint32_t*)&hi;
    return r;
}
__device__ __forceinline__ void cp16(uint32_t dst, const void* src) {
    asm volatile("cp.async.cg.shared.global [%0], [%1], 16;"
                 :: "r"(dst), "l"(src) : "memory");
}
__device__ __forceinline__ void cp16z(uint32_t dst, const void* src, int sz) {
    asm volatile("cp.async.cg.shared.global [%0], [%1], 16, %2;"
                 :: "r"(dst), "l"(src), "r"(sz) : "memory");
}
__device__ __forceinline__ void cp_commit() { asm volatile("cp.async.commit_group;" ::: "memory"); }
__device__ __forceinline__ void cp_wait1()  { asm volatile("cp.async.wait_group 1;" ::: "memory"); }

__device__ __forceinline__ void mma16(float c[4], const uint32_t a[4], uint32_t b0, uint32_t b1) {
    asm volatile(
        "mma.sync.aligned.m16n8k16.row.col.f32.f16.f16.f32 "
        "{%0,%1,%2,%3}, {%4,%5,%6,%7}, {%8,%9}, {%0,%1,%2,%3};"
        : "+f"(c[0]), "+f"(c[1]), "+f"(c[2]), "+f"(c[3])
        : "r"(a[0]), "r"(a[1]), "r"(a[2]), "r"(a[3]), "r"(b0), "r"(b1));
}
__device__ __forceinline__ void ldsm_x4(uint32_t r[4], uint32_t addr) {
    asm volatile("ldmatrix.sync.aligned.m8n8.x4.shared.b16 {%0,%1,%2,%3}, [%4];"
                 : "=r"(r[0]), "=r"(r[1]), "=r"(r[2]), "=r"(r[3]) : "r"(addr));
}
__device__ __forceinline__ void ldsm_x4_t(uint32_t r[4], uint32_t addr) {
    asm volatile("ldmatrix.sync.aligned.m8n8.x4.trans.shared.b16 {%0,%1,%2,%3}, [%4];"
                 : "=r"(r[0]), "=r"(r[1]), "=r"(r[2]), "=r"(r[3]) : "r"(addr));
}

// ---------------- fused reset + out-zero + fp16 conversion ----------------
#define XN4  (NTOK * D_MODEL / 4)                  // 2097152
#define WN4  (N_EXP * D_MODEL * D_HIDDEN / 4)      // 4194304
#define CONV_TOTAL (XN4 + 3 * WN4)                 // 14680064

__global__ void prep_kernel(const float* __restrict__ x,
                            const float* __restrict__ w1,
                            const float* __restrict__ w2,
                            const float* __restrict__ w3,
                            float* __restrict__ out, int out_n) {
    int i = blockIdx.x * blockDim.x + threadIdx.x;
    if (i < MAXROWS) {
        g_row_token[i] = -1;
        g_row_prob[i]  = 0.0f;
        g_row_expert[i] = 0;
    }
    if (i < N_EXP) {
        g_count[i] = 0;
        g_fill[i] = 0;
        g_importance[i] = 0.0f;
    }
    if (i < out_n) out[i] = 0.0f;
    if (i < CONV_TOTAL) {
        const float* src;
        __half* dst;
        int j;
        if (i < XN4)               { src = x;  dst = g_xh;  j = i; }
        else if (i < XN4 + WN4)    { src = w1; dst = g_w1h; j = i - XN4; }
        else if (i < XN4 + 2*WN4)  { src = w2; dst = g_w2h; j = i - XN4 - WN4; }
        else                       { src = w3; dst = g_w3h; j = i - XN4 - 2*WN4; }
        float4 v = ((const float4*)src)[j];
        *(uint2*)(dst + (size_t)j * 4) = f4_to_h4(v);
    }
}

// ---------------- router: one warp per token ----------------
__global__ void router_kernel(const float* __restrict__ x,
                              const float* __restrict__ gate_w,
                              const float* __restrict__ gate_b) {
    __shared__ float s_imp[N_EXP];
    __shared__ int   s_cnt[N_EXP];
    if (threadIdx.x < N_EXP) { s_imp[threadIdx.x] = 0.0f; s_cnt[threadIdx.x] = 0; }
    __syncthreads();

    int gwarp = (blockIdx.x * blockDim.x + threadIdx.x) >> 5;
    int lane  = threadIdx.x & 31;

    if (gwarp < NTOK) {
        int t = gwarp;
        float acc[N_EXP];
#pragma unroll
        for (int e = 0; e < N_EXP; e++) acc[e] = 0.0f;

        const float* xr = x + (size_t)t * D_MODEL;
        for (int d = lane; d < D_MODEL; d += 32) {
            float xv = xr[d];
            float4 g0 = *(const float4*)(gate_w + (size_t)d * N_EXP);
            float4 g1 = *(const float4*)(gate_w + (size_t)d * N_EXP + 4);
            acc[0] += xv * g0.x; acc[1] += xv * g0.y;
            acc[2] += xv * g0.z; acc[3] += xv * g0.w;
            acc[4] += xv * g1.x; acc[5] += xv * g1.y;
            acc[6] += xv * g1.z; acc[7] += xv * g1.w;
        }
#pragma unroll
        for (int off = 16; off > 0; off >>= 1) {
#pragma unroll
            for (int e = 0; e < N_EXP; e++)
                acc[e] += __shfl_xor_sync(0xffffffffu, acc[e], off);
        }

        if (lane == 0) {
            float logits[N_EXP];
#pragma unroll
            for (int e = 0; e < N_EXP; e++) logits[e] = acc[e] + gate_b[e];

            float m = logits[0];
#pragma unroll
            for (int e = 1; e < N_EXP; e++) m = fmaxf(m, logits[e]);
            float p[N_EXP], s = 0.0f;
#pragma unroll
            for (int e = 0; e < N_EXP; e++) { p[e] = expf(logits[e] - m); s += p[e]; }
            float inv = 1.0f / s;
#pragma unroll
            for (int e = 0; e < N_EXP; e++) atomicAdd(&s_imp[e], p[e] * inv);

            int i1 = 0; float m1 = logits[0];
#pragma unroll
            for (int e = 1; e < N_EXP; e++)
                if (logits[e] > m1) { m1 = logits[e]; i1 = e; }
            int i2 = -1; float m2 = -INFINITY;
#pragma unroll
            for (int e = 0; e < N_EXP; e++)
                if (e != i1 && logits[e] > m2) { m2 = logits[e]; i2 = e; }

            float p1 = 1.0f / (1.0f + expf(m2 - m1));
            g_tok_idx[t * 2]     = i1;
            g_tok_idx[t * 2 + 1] = i2;
            g_tok_prob[t * 2]     = p1;
            g_tok_prob[t * 2 + 1] = 1.0f - p1;
            atomicAdd(&s_cnt[i1], 1);
            atomicAdd(&s_cnt[i2], 1);
        }
    }
    __syncthreads();
    if (threadIdx.x < N_EXP) {
        atomicAdd(&g_importance[threadIdx.x], s_imp[threadIdx.x]);
        atomicAdd(&g_count[threadIdx.x], s_cnt[threadIdx.x]);
    }
}

// ---------------- fused scan + fill + scatter ----------------
__global__ void fill_scatter_kernel() {
    int i = blockIdx.x * blockDim.x + threadIdx.x;
    int seg[N_EXP];
    {
        int off = 0;
#pragma unroll
        for (int e = 0; e < N_EXP; e++) {
            seg[e] = off;
            off += ((g_count[e] + BM - 1) / BM) * BM;
        }
    }
    if (i < MAXROWS) {
        int e = 0;
#pragma unroll
        for (int ee = 1; ee < N_EXP; ee++)
            if (i >= seg[ee]) e = ee;
        g_row_expert[i] = e;
    }
    if (i < NPAIR) {
        int e = g_tok_idx[i];
        int slot = atomicAdd(&g_fill[e], 1);
        int r = seg[e] + slot;
        g_row_token[r] = i >> 1;
        g_row_prob[r]  = g_tok_prob[i];
    }
}

// ---------------- Stage A: h = silu(X w1 + b1) * (X w2 + b2) ----------------
// 128x64(x2), warps 4m x 2n, BK=64 (4 k16-steps), 3-stage cp.async,
// ONE barrier per 64-k chunk, fp16 mma m16n8k16.
__global__ void __launch_bounds__(256, 2) stageA_kernel(
    const float* __restrict__ b1, const float* __restrict__ b2)
{
    extern __shared__ __half smem[];
    __shared__ int s_tok[BM];

    const int tid = threadIdx.x;
    const int m0 = blockIdx.x * BM;
    const int n0 = blockIdx.y * BNA;
    const int e  = g_row_expert[m0];

    if (tid < BM) s_tok[tid] = g_row_token[m0 + tid];
    __syncthreads();

    const uint32_t xs0  = smem_u32(smem);
    const uint32_t w1s0 = xs0 + NSTG * XS_STAGE;
    const uint32_t w2s0 = w1s0 + NSTG * WA_STAGE;

    // X tile: 128 rows x 128B = 1024 granules -> 4/thread
    const __half* xsrc[4];
    int xsz[4];
    uint32_t xdst[4];
#pragma unroll
    for (int l = 0; l < 4; l++) {
        int idx = tid + l * 256;
        int r = idx >> 3, g = idx & 7;
        int tok = s_tok[r];
        xsrc[l] = (tok >= 0) ? (g_xh + (size_t)tok * D_MODEL + g * 8) : g_xh;
        xsz[l]  = (tok >= 0) ? 16 : 0;
        xdst[l] = (uint32_t)((r * XPH + g * 8) * 2);
    }
    // W tiles: 64 rows x 128B = 512 granules -> 2/thread each
    int wk[2], wg[2];
#pragma unroll
    for (int l = 0; l < 2; l++) {
        int idx = tid + l * 256;
        wk[l] = idx >> 3;
        wg[l] = (idx & 7) * 8;
    }
    const __half* w1b = g_w1h + (size_t)e * D_MODEL * D_HIDDEN + n0;
    const __half* w2b = g_w2h + (size_t)e * D_MODEL * D_HIDDEN + n0;

    const int lane = tid & 31, wid = tid >> 5;
    const int wm = wid & 3, wn = wid >> 2;     // 4 m-warps x 2 n-warps
    const int qr = lane >> 2, qc = lane & 3;

    const uint32_t aBase = xs0 +
        (uint32_t)(((wm * 32 + (lane & 15)) * XPH + (lane >> 4) * 8) * 2);
    const uint32_t bOff =
        (uint32_t)(((((lane & 7) + ((lane >> 3) & 1) * 8)) * WPHA + wn * 32 + (lane >> 4) * 8) * 2);

    auto issueA = [&](int c, int buf) {
        int k0 = c * BK;
#pragma unroll
        for (int l = 0; l < 4; l++)
            cp16z(xs0 + buf * XS_STAGE + xdst[l], xsrc[l] + k0, xsz[l]);
#pragma unroll
        for (int l = 0; l < 2; l++) {
            uint32_t d = (uint32_t)((wk[l] * WPHA + wg[l]) * 2);
            cp16(w1s0 + buf * WA_STAGE + d, w1b + (size_t)(k0 + wk[l]) * D_HIDDEN + wg[l]);
            cp16(w2s0 + buf * WA_STAGE + d, w2b + (size_t)(k0 + wk[l]) * D_HIDDEN + wg[l]);
        }
    };

    float acc1[2][4][4] = {};
    float acc2[2][4][4] = {};

    issueA(0, 0); cp_commit();
    issueA(1, 1); cp_commit();

    const int NCHUNK = D_MODEL / BK;   // 16
    for (int c = 0; c < NCHUNK; c++) {
        const int cur = c % NSTG;
        cp_wait1();
        __syncthreads();
#pragma unroll
        for (int step = 0; step < 4; step++) {
            const int kb = step * 16;
            uint32_t a[2][4];
#pragma unroll
            for (int mt = 0; mt < 2; mt++)
                ldsm_x4(a[mt], aBase + cur * XS_STAGE + (uint32_t)((mt * 16 * XPH + kb) * 2));
#pragma unroll
            for (int p = 0; p < 2; p++) {
                uint32_t t1[4], t2[4];
                uint32_t off = bOff + (uint32_t)((kb * WPHA + p * 16) * 2);
                ldsm_x4_t(t1, w1s0 + cur * WA_STAGE + off);
                ldsm_x4_t(t2, w2s0 + cur * WA_STAGE + off);
#pragma unroll
                for (int mt = 0; mt < 2; mt++) {
                    mma16(acc1[mt][2 * p],     a[mt], t1[0], t1[1]);
                    mma16(acc1[mt][2 * p + 1], a[mt], t1[2], t1[3]);
                    mma16(acc2[mt][2 * p],     a[mt], t2[0], t2[1]);
                    mma16(acc2[mt][2 * p + 1], a[mt], t2[2], t2[3]);
                }
            }
        }
        // buffer (c+2)%3 was consumed at iter c-1; top barrier fences it.
        if (c + 2 < NCHUNK) issueA(c + 2, (c + 2) % NSTG);
        cp_commit();
    }

    // epilogue
#pragma unroll
    for (int mt = 0; mt < 2; mt++) {
#pragma unroll
        for (int nt = 0; nt < 4; nt++) {
            int colg = n0 + wn * 32 + nt * 8 + 2 * qc;
            float bg0 = b1[e * D_HIDDEN + colg],     bu0 = b2[e * D_HIDDEN + colg];
            float bg1 = b1[e * D_HIDDEN + colg + 1], bu1 = b2[e * D_HIDDEN + colg + 1];
#pragma unroll
            for (int h = 0; h < 2; h++) {
                int row = m0 + wm * 32 + mt * 16 + qr + h * 8;
                float g0 = acc1[mt][nt][2 * h]     + bg0;
                float u0 = acc2[mt][nt][2 * h]     + bu0;
                float g1 = acc1[mt][nt][2 * h + 1] + bg1;
                float u1 = acc2[mt][nt][2 * h + 1] + bu1;
                float h0 = (g0 / (1.0f + expf(-g0))) * u0;
                float h1 = (g1 / (1.0f + expf(-g1))) * u1;
                *(__half2*)&g_hbuf[(size_t)row * D_HIDDEN + colg] =
                    __floats2half2_rn(h0, h1);
            }
        }
    }
}

// ---------------- Stage B: out += prob * (H w3 + b3) ----------------
__global__ void __launch_bounds__(256, 2) stageB_kernel(
    const float* __restrict__ b3, float* __restrict__ out)
{
    extern __shared__ __half smem[];
    __shared__ int   s_tok[BM];
    __shared__ float s_prob[BM];

    const int tid = threadIdx.x;
    const int m0 = blockIdx.x * BM;
    const int n0 = blockIdx.y * BNB;
    const int e  = g_row_expert[m0];

    if (tid < BM) {
        s_tok[tid]  = g_row_token[m0 + tid];
        s_prob[tid] = g_row_prob[m0 + tid];
    }
    __syncthreads();

    const uint32_t hs0  = smem_u32(smem);
    const uint32_t w3s0 = hs0 + NSTG * XS_STAGE;

    // H tile: 1024 granules -> 4/thread
    uint32_t hdst[4];
    const __half* hsrc[4];
#pragma unroll
    for (int l = 0; l < 4; l++) {
        int idx = tid + l * 256;
        int r = idx >> 3, g = idx & 7;
        hsrc[l] = g_hbuf + (size_t)(m0 + r) * D_HIDDEN + g * 8;
        hdst[l] = (uint32_t)((r * XPH + g * 8) * 2);
    }
    // W3 tile: 64 rows x 256B = 1024 granules -> 4/thread
    uint32_t w3dst[4];
    const __half* w3src[4];
#pragma unroll
    for (int l = 0; l < 4; l++) {
        int idx = tid + l * 256;
        int k = idx >> 4, g = (idx & 15) * 8;
        w3src[l] = g_w3h + (size_t)e * D_HIDDEN * D_MODEL + (size_t)k * D_MODEL + n0 + g;
        w3dst[l] = (uint32_t)((k * WPHB + g) * 2);
    }

    const int lane = tid & 31, wid = tid >> 5;
    const int wm = wid & 3, wn = wid >> 2;
    const int qr = lane >> 2, qc = lane & 3;

    const uint32_t aBase = hs0 +
        (uint32_t)(((wm * 32 + (lane & 15)) * XPH + (lane >> 4) * 8) * 2);
    const uint32_t bOff =
        (uint32_t)(((((lane & 7) + ((lane >> 3) & 1) * 8)) * WPHB + wn * 64 + (lane >> 4) * 8) * 2);

    auto issueB = [&](int c, int buf) {
        int k0 = c * BK;
#pragma unroll
        for (int l = 0; l < 4; l++)
            cp16(hs0 + buf * XS_STAGE + hdst[l], hsrc[l] + k0);
#pragma unroll
        for (int l = 0; l < 4; l++)
            cp16(w3s0 + buf * WB_STAGE + w3dst[l], w3src[l] + (size_t)k0 * D_MODEL);
    };

    float acc[2][8][4] = {};

    issueB(0, 0); cp_commit();
    issueB(1, 1); cp_commit();

    const int NCHUNK = D_HIDDEN / BK;   // 32
    for (int c = 0; c < NCHUNK; c++) {
        const int cur = c % NSTG;
        cp_wait1();
        __syncthreads();
#pragma unroll
        for (int step = 0; step < 4; step++) {
            const int kb = step * 16;
            uint32_t a[2][4];
#pragma unroll
            for (int mt = 0; mt < 2; mt++)
                ldsm_x4(a[mt], aBase + cur * XS_STAGE + (uint32_t)((mt * 16 * XPH + kb) * 2));
#pragma unroll
            for (int p = 0; p < 4; p++) {
                uint32_t t[4];
                ldsm_x4_t(t, w3s0 + cur * WB_STAGE + bOff + (uint32_t)((kb * WPHB + p * 16) * 2));
#pragma unroll
                for (int mt = 0; mt < 2; mt++) {
                    mma16(acc[mt][2 * p],     a[mt], t[0], t[1]);
                    mma16(acc[mt][2 * p + 1], a[mt], t[2], t[3]);
                }
            }
        }
        if (c + 2 < NCHUNK) issueB(c + 2, (c + 2) % NSTG);
        cp_commit();
    }

#pragma unroll
    for (int mt = 0; mt < 2; mt++) {
#pragma unroll
        for (int nt = 0; nt < 8; nt++) {
            int colg = n0 + wn * 64 + nt * 8 + 2 * qc;
            float bv0 = b3[e * D_MODEL + colg];
            float bv1 = b3[e * D_MODEL + colg + 1];
#pragma unroll
            for (int h = 0; h < 2; h++) {
                int rloc = wm * 32 + mt * 16 + qr + h * 8;
                int tok = s_tok[rloc];
                if (tok < 0) continue;
                float p = s_prob[rloc];
                atomicAdd(&out[(size_t)tok * D_MODEL + colg],
                          p * (acc[mt][nt][2 * h] + bv0));
                atomicAdd(&out[(size_t)tok * D_MODEL + colg + 1],
                          p * (acc[mt][nt][2 * h + 1] + bv1));
            }
        }
    }
}

// ---------------- aux loss ----------------
__global__ void aux_kernel(float* out) {
    if (threadIdx.x == 0 && blockIdx.x == 0) {
        float a = 0.0f;
        for (int e = 0; e < N_EXP; e++) {
            float imp = g_importance[e] / (float)NTOK;
            float load = (float)g_count[e] / (float)NPAIR;
            a += imp * load;
        }
        out[(size_t)NTOK * D_MODEL] = a * (float)N_EXP;
    }
}

// ---------------- launch ----------------
extern "C" void kernel_launch(void* const* d_in, const int* in_sizes, int n_in,
                              void* d_out, int out_size) {
    const float* x      = (const float*)d_in[0];
    const float* gate_w = (const float*)d_in[1];
    const float* gate_b = (const float*)d_in[2];
    const float* w1     = (const float*)d_in[3];
    const float* b1     = (const float*)d_in[4];
    const float* w2     = (const float*)d_in[5];
    const float* b2     = (const float*)d_in[6];
    const float* w3     = (const float*)d_in[7];
    const float* b3     = (const float*)d_in[8];
    float* out = (float*)d_out;

    cudaFuncSetAttribute(stageA_kernel, cudaFuncAttributeMaxDynamicSharedMemorySize, SMEM_A);
    cudaFuncSetAttribute(stageB_kernel, cudaFuncAttributeMaxDynamicSharedMemorySize, SMEM_B);

    // launch index 3 = stageA (ncu capture slot)
    prep_kernel<<<(CONV_TOTAL + 255) / 256, 256>>>(x, w1, w2, w3, out, out_size);
    router_kernel<<<NTOK / 8, 256>>>(x, gate_w, gate_b);
    fill_scatter_kernel<<<(MAXROWS + 255) / 256, 256>>>();
    stageA_kernel<<<dim3(MTILES, D_HIDDEN / BNA), 256, SMEM_A>>>(b1, b2);
    stageB_kernel<<<dim3(MTILES, D_MODEL / BNB), 256, SMEM_B>>>(b3, out);
    if (out_size > NTOK * D_MODEL) {
        aux_kernel<<<1, 32>>>(out);
    }
}